// round 6
// baseline (speedup 1.0000x reference)
#include <cuda_runtime.h>

// GC_3D loss via product-sum expansion:
//   dot_k = (P-Uq) + (P-Up) - XY_k,  den_k = (T2-Vq) + (T2-Vp) - 2*TB_k
// Hot loop accumulates only XY_k, TB_k (3 fma/offset/voxel), P, T2, BCE.
// Boundary corrections from 26 face/edge/corner region sums (aux kernel).

#define DX 192
#define DY 192
#define DZ 128
#define DXY (DX * DY)
#define NX4 48
#define NACC 29   // XY[13], TB[13], P, T2, BCE
#define ZCHUNKS 4
#define ZSTEP (DZ / ZCHUNKS)   // 32

__device__ double g_sums[NACC];
__device__ double g_regII[27];   // region sums of i*t,  index = zs*9+ys*3+xs
__device__ double g_regTT[27];   // region sums of t*t   (sel: 0 free, 1 low, 2 high)

__global__ void gc3d_zero_kernel() {
    int i = threadIdx.x;
    if (i < NACC) g_sums[i] = 0.0;
    if (i < 27) { g_regII[i] = 0.0; g_regTT[i] = 0.0; }
}

// ---- boundary region sums: 26 regions x (i*t, t*t) ----
__global__ void __launch_bounds__(256) gc3d_region_kernel(
    const float* __restrict__ in, const float* __restrict__ tg)
{
    const int r     = (blockIdx.x % 26) + 1;   // 1..26
    const int slice = blockIdx.x / 26;         // 0..7
    const int zs = r / 9, ys = (r / 3) % 3, xs = r % 3;
    const int zv = (zs == 1) ? 0 : DZ - 1;
    const int yv = (ys == 1) ? 0 : DY - 1;
    const int xv = (xs == 1) ? 0 : DX - 1;
    const int nz = zs ? 1 : DZ, ny = ys ? 1 : DY, nx = xs ? 1 : DX;
    const long total = 4L * nz * ny * nx;

    float sII = 0.0f, sTT = 0.0f;
    for (long e = (long)slice * blockDim.x + threadIdx.x; e < total; e += 8L * blockDim.x) {
        long t = e;
        int x, y, z, b;
        if (xs) x = xv; else { x = (int)(t % DX); t /= DX; }
        if (ys) y = yv; else { y = (int)(t % DY); t /= DY; }
        if (zs) z = zv; else { z = (int)(t % DZ); t /= DZ; }
        b = (int)t;
        const int idx = ((b * DZ + z) * DY + y) * DX + x;
        const float iv = in[idx], tv = tg[idx];
        sII = fmaf(iv, tv, sII);
        sTT = fmaf(tv, tv, sTT);
    }
    for (int o = 16; o > 0; o >>= 1) {
        sII += __shfl_xor_sync(0xFFFFFFFFu, sII, o);
        sTT += __shfl_xor_sync(0xFFFFFFFFu, sTT, o);
    }
    __shared__ float shI[8], shT[8];
    const int wid = threadIdx.x >> 5, lid = threadIdx.x & 31;
    if (lid == 0) { shI[wid] = sII; shT[wid] = sTT; }
    __syncthreads();
    if (threadIdx.x == 0) {
        float a = 0.0f, c = 0.0f;
        for (int w = 0; w < 8; ++w) { a += shI[w]; c += shT[w]; }
        atomicAdd(&g_regII[r], (double)a);
        atomicAdd(&g_regTT[r], (double)c);
    }
}

// ---- main kernel ----
// window load, zero-padded at x-edges via SEL (alu pipe)
__device__ __forceinline__ void ldwin(const float* __restrict__ p,
                                      int o_m1, int o_p4, bool xm, bool xp,
                                      float w[6]) {
    float4 v = *reinterpret_cast<const float4*>(p);
    float a = __ldg(p + o_m1);
    float bq = __ldg(p + o_p4);
    w[0] = xm ? a : 0.0f;
    w[1] = v.x; w[2] = v.y; w[3] = v.z; w[4] = v.w;
    w[5] = xp ? bq : 0.0f;
}

__device__ __forceinline__ void zrow(float w[6], bool ok) {
#pragma unroll
    for (int j = 0; j < 6; ++j) w[j] = ok ? w[j] : 0.0f;
}

// One (row,dx): XY += i_n*t_c + i_c*t_n ; TB += t_n*t_c   (3 fma x 4 voxels)
#define ACC3(WI, WT, J, XYA, TBA) do {                                        \
    XYA = fmaf((WI)[(J)+0], cT0, XYA); XYA = fmaf(cI0, (WT)[(J)+0], XYA);     \
    TBA = fmaf((WT)[(J)+0], cT0, TBA);                                        \
    XYA = fmaf((WI)[(J)+1], cT1, XYA); XYA = fmaf(cI1, (WT)[(J)+1], XYA);     \
    TBA = fmaf((WT)[(J)+1], cT1, TBA);                                        \
    XYA = fmaf((WI)[(J)+2], cT2, XYA); XYA = fmaf(cI2, (WT)[(J)+2], XYA);     \
    TBA = fmaf((WT)[(J)+2], cT2, TBA);                                        \
    XYA = fmaf((WI)[(J)+3], cT3, XYA); XYA = fmaf(cI3, (WT)[(J)+3], XYA);     \
    TBA = fmaf((WT)[(J)+3], cT3, TBA);                                        \
} while (0)

#define ROW3(WI, WT, K) do {                                                  \
    ACC3(WI, WT, 0, xy[(K)],   tb[(K)]);                                      \
    ACC3(WI, WT, 1, xy[(K)+1], tb[(K)+1]);                                    \
    ACC3(WI, WT, 2, xy[(K)+2], tb[(K)+2]);                                    \
} while (0)

// center-voxel work: P += i*t, T2 += t*t, bce (log2 domain)
#define CENTER4(CI, CT) do {                                                  \
    P  = fmaf(CI[1], CT[1], P);  P  = fmaf(CI[2], CT[2], P);                  \
    P  = fmaf(CI[3], CT[3], P);  P  = fmaf(CI[4], CT[4], P);                  \
    T2 = fmaf(CT[1], CT[1], T2); T2 = fmaf(CT[2], CT[2], T2);                 \
    T2 = fmaf(CT[3], CT[3], T2); T2 = fmaf(CT[4], CT[4], T2);                 \
    float l1, l2;                                                             \
    l1 = __log2f(CI[1]); l2 = __log2f(1.0f - CI[1]); bce += l2 + CT[1]*(l1-l2); \
    l1 = __log2f(CI[2]); l2 = __log2f(1.0f - CI[2]); bce += l2 + CT[2]*(l1-l2); \
    l1 = __log2f(CI[3]); l2 = __log2f(1.0f - CI[3]); bce += l2 + CT[3]*(l1-l2); \
    l1 = __log2f(CI[4]); l2 = __log2f(1.0f - CI[4]); bce += l2 + CT[4]*(l1-l2); \
} while (0)

template<bool YG>
__device__ __forceinline__ void gc3d_march(
    const float* __restrict__ in, const float* __restrict__ tg,
    int base, int nsteps, bool do_epi,
    int o_m1, int o_p4, bool xm, bool xp,
    int dUp, int dDn, bool ymOK, bool ypOK,
    float* xy, float* tb, float& P, float& T2, float& bce)
{
    float CWi[6], CWt[6], UWi[6], UWt[6];
    ldwin(in + base,       o_m1, o_p4, xm, xp, CWi);
    ldwin(tg + base,       o_m1, o_p4, xm, xp, CWt);
    ldwin(in + base + dUp, o_m1, o_p4, xm, xp, UWi);
    ldwin(tg + base + dUp, o_m1, o_p4, xm, xp, UWt);
    if (YG) { zrow(UWi, ypOK); zrow(UWt, ypOK); }

#pragma unroll 2
    for (int s = 0; s < nsteps; ++s) {
        const int baseN = base + DXY;
        float NmI[6], NmT[6], NcI[6], NcT[6], NpI[6], NpT[6];
        ldwin(in + baseN + dDn, o_m1, o_p4, xm, xp, NmI);
        ldwin(tg + baseN + dDn, o_m1, o_p4, xm, xp, NmT);
        ldwin(in + baseN,       o_m1, o_p4, xm, xp, NcI);
        ldwin(tg + baseN,       o_m1, o_p4, xm, xp, NcT);
        ldwin(in + baseN + dUp, o_m1, o_p4, xm, xp, NpI);
        ldwin(tg + baseN + dUp, o_m1, o_p4, xm, xp, NpT);
        if (YG) {
            zrow(NmI, ymOK); zrow(NmT, ymOK);
            zrow(NpI, ypOK); zrow(NpT, ypOK);
        }

        const float cI0 = CWi[1], cI1 = CWi[2], cI2 = CWi[3], cI3 = CWi[4];
        const float cT0 = CWt[1], cT1 = CWt[2], cT2 = CWt[3], cT3 = CWt[4];

        CENTER4(CWi, CWt);

        // k0: (0,0,+1) on center row
        ACC3(CWi, CWt, 2, xy[0], tb[0]);
        // k1..3: (0,1,dx) on carried y+1 row
        ROW3(UWi, UWt, 1);
        // k4..6: (1,-1,dx)
        ROW3(NmI, NmT, 4);
        // k7..9: (1,0,dx)
        ROW3(NcI, NcT, 7);
        // k10..12: (1,1,dx)
        ROW3(NpI, NpT, 10);

#pragma unroll
        for (int j = 0; j < 6; ++j) {
            CWi[j] = NcI[j]; CWt[j] = NcT[j];
            UWi[j] = NpI[j]; UWt[j] = NpT[j];
        }
        base = baseN;
    }

    if (do_epi) {  // z = 127: only dz=0 offsets; no fresh loads
        const float cI0 = CWi[1], cI1 = CWi[2], cI2 = CWi[3], cI3 = CWi[4];
        const float cT0 = CWt[1], cT1 = CWt[2], cT2 = CWt[3], cT3 = CWt[4];
        CENTER4(CWi, CWt);
        ACC3(CWi, CWt, 2, xy[0], tb[0]);
        ROW3(UWi, UWt, 1);
    }
}

__global__ void __launch_bounds__(128) gc3d_main_kernel(
    const float* __restrict__ in, const float* __restrict__ tg)
{
    const int tid = blockIdx.x * blockDim.x + threadIdx.x;   // 0..147455
    const int x4 = tid % NX4;
    const int y  = (tid / NX4) % DY;
    const int t2i = tid / (NX4 * DY);   // 0..15
    const int zc = t2i & 3;
    const int b  = t2i >> 2;
    const int z0 = zc * ZSTEP;

    int base = ((b * DZ + z0) * DY + y) * DX + x4 * 4;

    const int  o_m1 = (x4 == 0)       ? 0 : -1;
    const int  o_p4 = (x4 == NX4 - 1) ? 3 : 4;
    const bool xm   = (x4 != 0);
    const bool xp   = (x4 != NX4 - 1);
    const int  dUp  = (y == DY - 1) ? 0 : DX;
    const int  dDn  = (y == 0)      ? 0 : -DX;
    const bool ymOK = (y != 0);
    const bool ypOK = (y != DY - 1);

    const int  nsteps = (zc == ZCHUNKS - 1) ? (ZSTEP - 1) : ZSTEP;
    const bool do_epi = (zc == ZCHUNKS - 1);

    float xy[13], tb[13], P = 0.0f, T2 = 0.0f, bce = 0.0f;
#pragma unroll
    for (int k = 0; k < 13; ++k) { xy[k] = 0.0f; tb[k] = 0.0f; }

    if (y == 0 || y == DY - 1)
        gc3d_march<true >(in, tg, base, nsteps, do_epi, o_m1, o_p4, xm, xp,
                          dUp, dDn, ymOK, ypOK, xy, tb, P, T2, bce);
    else
        gc3d_march<false>(in, tg, base, nsteps, do_epi, o_m1, o_p4, xm, xp,
                          dUp, dDn, ymOK, ypOK, xy, tb, P, T2, bce);

    float acc[NACC];
#pragma unroll
    for (int k = 0; k < 13; ++k) { acc[k] = xy[k]; acc[13 + k] = tb[k]; }
    acc[26] = P; acc[27] = T2; acc[28] = bce;

#pragma unroll
    for (int i = 0; i < NACC; ++i) {
        float v = acc[i];
#pragma unroll
        for (int o = 16; o > 0; o >>= 1) v += __shfl_xor_sync(0xFFFFFFFFu, v, o);
        acc[i] = v;
    }

    __shared__ float sh[4][NACC];
    const int wid = threadIdx.x >> 5;
    const int lid = threadIdx.x & 31;
    if (lid == 0) {
#pragma unroll
        for (int i = 0; i < NACC; ++i) sh[wid][i] = acc[i];
    }
    __syncthreads();
    if (wid == 0 && lid < NACC) {
        float v = sh[0][lid] + sh[1][lid] + sh[2][lid] + sh[3][lid];
        atomicAdd(&g_sums[lid], (double)v);
    }
}

// inclusion-exclusion over excluded faces (sel: 0 none, 1 low, 2 high)
__device__ double excl_union(const double* reg, int sz, int sy, int sx) {
    double u = 0.0;
    if (sz) u += reg[sz * 9];
    if (sy) u += reg[sy * 3];
    if (sx) u += reg[sx];
    if (sz && sy) u -= reg[sz * 9 + sy * 3];
    if (sz && sx) u -= reg[sz * 9 + sx];
    if (sy && sx) u -= reg[sy * 3 + sx];
    if (sz && sy && sx) u += reg[sz * 9 + sy * 3 + sx];
    return u;
}

__global__ void gc3d_finalize_kernel(float* out, double inv_n) {
    if (threadIdx.x == 0 && blockIdx.x == 0) {
        const int dzs[13] = {0, 0, 0, 0,  1, 1, 1, 1, 1, 1, 1, 1, 1};
        const int dys[13] = {0, 1, 1, 1, -1,-1,-1, 0, 0, 0, 1, 1, 1};
        const int dxs[13] = {1,-1, 0, 1, -1, 0, 1,-1, 0, 1,-1, 0, 1};
        const double P  = g_sums[26];
        const double T2 = g_sums[27];
        double accv = 0.0;
        for (int k = 0; k < 13; ++k) {
            const int dz = dzs[k], dy = dys[k], dx = dxs[k];
            // neighbor(q)-side exclusions: dz=1 -> z low; dy=+1 -> y low, -1 -> y high; same for x
            const int qz = dz ? 1 : 0;
            const int qy = (dy == 1) ? 1 : ((dy == -1) ? 2 : 0);
            const int qx = (dx == 1) ? 1 : ((dx == -1) ? 2 : 0);
            // center(p)-side exclusions: mirrored
            const int pz = dz ? 2 : 0;
            const int py = (dy == 1) ? 2 : ((dy == -1) ? 1 : 0);
            const int px = (dx == 1) ? 2 : ((dx == -1) ? 1 : 0);

            const double Aq = P  - excl_union(g_regII, qz, qy, qx);
            const double Ap = P  - excl_union(g_regII, pz, py, px);
            const double Vq = T2 - excl_union(g_regTT, qz, qy, qx);
            const double Vp = T2 - excl_union(g_regTT, pz, py, px);

            const double dot = Aq + Ap - g_sums[k];
            const double den = Vq + Vp - 2.0 * g_sums[13 + k];
            accv += dot / (den + 1e-5);
        }
        const double bce = -g_sums[28] * inv_n * 0.6931471805599453; // log2 -> ln
        out[0] = (float)(bce + 1.0 - accv / 13.0);
    }
}

extern "C" void kernel_launch(void* const* d_in, const int* in_sizes, int n_in,
                              void* d_out, int out_size)
{
    const float* in = (const float*)d_in[0];
    const float* tg = (const float*)d_in[1];
    float* out = (float*)d_out;
    const int n = in_sizes[0];   // 18874368

    gc3d_zero_kernel<<<1, 32>>>();
    gc3d_region_kernel<<<208, 256>>>(in, tg);     // 26 regions x 8 slices
    gc3d_main_kernel<<<1152, 128>>>(in, tg);
    gc3d_finalize_kernel<<<1, 32>>>(out, 1.0 / (double)n);
}

// round 7
// speedup vs baseline: 1.3036x; 1.3036x over previous
#include <cuda_runtime.h>

// GC_3D loss: BCE(mean) + 1 - (1/13) * sum_k [ sum(di_k*dt_k) / (sum(dt_k^2)+1e-5) ]
// Shape (4,1,128,192,192) f32, forward-z canonical offsets.
// R7: R3 structure; x-edge guard FMULs removed (self-load => zero diff),
//     2-launch pipeline (per-block partials, no atomics/zeroing),
//     parallel finalize (27-warp reduce + 13 concurrent DP divides).

#define DX 192
#define DY 192
#define DZ 128
#define DXY (DX * DY)
#define NX4 48
#define NSUM 27
#define ZCHUNKS 4
#define ZSTEP (DZ / ZCHUNKS)   // 32
#define NBLK 1152

__device__ float g_part[NSUM][NBLK];   // fully overwritten each run

__device__ __forceinline__ void ldwin(const float* __restrict__ p,
                                      int o_m1, int o_p4, float w[6]) {
    float4 v = *reinterpret_cast<const float4*>(p);
    w[0] = __ldg(p + o_m1);   // x-edge: o_m1=0 -> w[0]=center -> diff 0
    w[1] = v.x; w[2] = v.y; w[3] = v.z; w[4] = v.w;
    w[5] = __ldg(p + o_p4);   // x-edge: o_p4=3 -> w[5]=center -> diff 0
}

// One (row,dx) offset: 4 diffs per array. G: multiply dt by row flag (y-edge path only).
#define ACCUM(WI, WT, J, G, RF, D, Q) do {                                  \
    float di0 = (WI)[(J)]   - cI0; float dt0 = (WI != WI ? 0.0f : ((WT)[(J)]   - cT0)); \
    float di1 = (WI)[(J)+1] - cI1; float dt1 = ((WT)[(J)+1] - cT1);         \
    float di2 = (WI)[(J)+2] - cI2; float dt2 = ((WT)[(J)+2] - cT2);         \
    float di3 = (WI)[(J)+3] - cI3; float dt3 = ((WT)[(J)+3] - cT3);         \
    if (G) { dt0 *= (RF); dt1 *= (RF); dt2 *= (RF); dt3 *= (RF); }          \
    D = fmaf(di0, dt0, D); D = fmaf(di1, dt1, D);                           \
    D = fmaf(di2, dt2, D); D = fmaf(di3, dt3, D);                           \
    Q = fmaf(dt0, dt0, Q); Q = fmaf(dt1, dt1, Q);                           \
    Q = fmaf(dt2, dt2, Q); Q = fmaf(dt3, dt3, Q);                           \
} while (0)

#define ROW3(WI, WT, G, RF, K) do {                                         \
    ACCUM(WI, WT, 0, G, RF, dot[(K)],   den[(K)]);                          \
    ACCUM(WI, WT, 1, G, RF, dot[(K)+1], den[(K)+1]);                        \
    ACCUM(WI, WT, 2, G, RF, dot[(K)+2], den[(K)+2]);                        \
} while (0)

// BCE partial in log2 domain: lg2(1-i) + t*(lg2(i)-lg2(1-i))
#define BCE4(CI, CT) do {                                                   \
    float l1, l2;                                                           \
    l1 = __log2f(CI[1]); l2 = __log2f(1.0f - CI[1]); bce += l2 + CT[1]*(l1-l2); \
    l1 = __log2f(CI[2]); l2 = __log2f(1.0f - CI[2]); bce += l2 + CT[2]*(l1-l2); \
    l1 = __log2f(CI[3]); l2 = __log2f(1.0f - CI[3]); bce += l2 + CT[3]*(l1-l2); \
    l1 = __log2f(CI[4]); l2 = __log2f(1.0f - CI[4]); bce += l2 + CT[4]*(l1-l2); \
} while (0)

template<bool YG>
__device__ __forceinline__ void gc3d_march(
    const float* __restrict__ in, const float* __restrict__ tg,
    int base, int nsteps, bool do_epi,
    int o_m1, int o_p4, int dUp, int dDn,
    float fym, float fyp,
    float* dot, float* den, float& bce)
{
    float CWi[6], CWt[6], UWi[6], UWt[6];      // carried: center row, y+1 row
    ldwin(in + base,       o_m1, o_p4, CWi);
    ldwin(tg + base,       o_m1, o_p4, CWt);
    ldwin(in + base + dUp, o_m1, o_p4, UWi);
    ldwin(tg + base + dUp, o_m1, o_p4, UWt);

#pragma unroll 2
    for (int s = 0; s < nsteps; ++s) {
        const int baseN = base + DXY;
        float NmI[6], NmT[6], NcI[6], NcT[6], NpI[6], NpT[6];
        ldwin(in + baseN + dDn, o_m1, o_p4, NmI);
        ldwin(tg + baseN + dDn, o_m1, o_p4, NmT);
        ldwin(in + baseN,       o_m1, o_p4, NcI);
        ldwin(tg + baseN,       o_m1, o_p4, NcT);
        ldwin(in + baseN + dUp, o_m1, o_p4, NpI);
        ldwin(tg + baseN + dUp, o_m1, o_p4, NpT);

        const float cI0 = CWi[1], cI1 = CWi[2], cI2 = CWi[3], cI3 = CWi[4];
        const float cT0 = CWt[1], cT1 = CWt[2], cT2 = CWt[3], cT3 = CWt[4];

        BCE4(CWi, CWt);

        // k0: (0,0,+1) on center row — never y-guarded, x-edges self-zero
        ACCUM(CWi, CWt, 2, false, 1.0f, dot[0], den[0]);
        // k1..3: (0,1,dx) on carried y+1 row
        ROW3(UWi, UWt, YG, fyp, 1);
        // k4..6: (1,-1,dx)
        ROW3(NmI, NmT, YG, fym, 4);
        // k7..9: (1,0,dx)
        ROW3(NcI, NcT, false, 1.0f, 7);
        // k10..12: (1,1,dx)
        ROW3(NpI, NpT, YG, fyp, 10);

#pragma unroll
        for (int j = 0; j < 6; ++j) {
            CWi[j] = NcI[j]; CWt[j] = NcT[j];
            UWi[j] = NpI[j]; UWt[j] = NpT[j];
        }
        base = baseN;
    }

    if (do_epi) {  // z = 127: only dz=0 offsets; no fresh loads
        const float cI0 = CWi[1], cI1 = CWi[2], cI2 = CWi[3], cI3 = CWi[4];
        const float cT0 = CWt[1], cT1 = CWt[2], cT2 = CWt[3], cT3 = CWt[4];
        BCE4(CWi, CWt);
        ACCUM(CWi, CWt, 2, false, 1.0f, dot[0], den[0]);
        ROW3(UWi, UWt, YG, fyp, 1);
    }
}

__global__ void __launch_bounds__(128) gc3d_main_kernel(
    const float* __restrict__ in, const float* __restrict__ tg)
{
    const int tid = blockIdx.x * blockDim.x + threadIdx.x;   // 0..147455
    const int x4 = tid % NX4;
    const int y  = (tid / NX4) % DY;
    const int t2 = tid / (NX4 * DY);   // 0..15
    const int zc = t2 & 3;
    const int b  = t2 >> 2;
    const int z0 = zc * ZSTEP;

    int base = ((b * DZ + z0) * DY + y) * DX + x4 * 4;

    const int   o_m1 = (x4 == 0)       ? 0 : -1;
    const int   o_p4 = (x4 == NX4 - 1) ? 3 : 4;
    const int   dUp  = (y == DY - 1) ? 0 : DX;
    const int   dDn  = (y == 0)      ? 0 : -DX;
    const float fyp  = (y == DY - 1) ? 0.0f : 1.0f;
    const float fym  = (y == 0)      ? 0.0f : 1.0f;

    const int  nsteps = (zc == ZCHUNKS - 1) ? (ZSTEP - 1) : ZSTEP;
    const bool do_epi = (zc == ZCHUNKS - 1);

    float dot[13], den[13], bce = 0.0f;
#pragma unroll
    for (int k = 0; k < 13; ++k) { dot[k] = 0.0f; den[k] = 0.0f; }

    if (y == 0 || y == DY - 1)
        gc3d_march<true >(in, tg, base, nsteps, do_epi, o_m1, o_p4, dUp, dDn,
                          fym, fyp, dot, den, bce);
    else
        gc3d_march<false>(in, tg, base, nsteps, do_epi, o_m1, o_p4, dUp, dDn,
                          fym, fyp, dot, den, bce);

    // pack 27 partials, warp butterfly, block reduce, overwrite block slot
    float acc[NSUM];
#pragma unroll
    for (int k = 0; k < 13; ++k) { acc[k] = dot[k]; acc[13 + k] = den[k]; }
    acc[26] = bce;

#pragma unroll
    for (int i = 0; i < NSUM; ++i) {
        float v = acc[i];
#pragma unroll
        for (int o = 16; o > 0; o >>= 1) v += __shfl_xor_sync(0xFFFFFFFFu, v, o);
        acc[i] = v;
    }

    __shared__ float sh[4][NSUM];
    const int wid = threadIdx.x >> 5;
    const int lid = threadIdx.x & 31;
    if (lid == 0) {
#pragma unroll
        for (int i = 0; i < NSUM; ++i) sh[wid][i] = acc[i];
    }
    __syncthreads();
    if (wid == 0 && lid < NSUM) {
        g_part[lid][blockIdx.x] = sh[0][lid] + sh[1][lid] + sh[2][lid] + sh[3][lid];
    }
}

// 27 warps: warp i reduces g_part[i][*] in double; 13 parallel DP divides.
__global__ void __launch_bounds__(864) gc3d_finalize_kernel(float* out, double inv_n) {
    const int wid = threadIdx.x >> 5;
    const int lid = threadIdx.x & 31;

    double s = 0.0;
    if (wid < NSUM) {
        for (int j = lid; j < NBLK; j += 32) s += (double)g_part[wid][j];
#pragma unroll
        for (int o = 16; o > 0; o >>= 1) s += __shfl_xor_sync(0xFFFFFFFFu, s, o);
    }

    __shared__ double sums[NSUM];
    __shared__ double ratios[13];
    if (wid < NSUM && lid == 0) sums[wid] = s;
    __syncthreads();

    if (threadIdx.x < 13)
        ratios[threadIdx.x] = sums[threadIdx.x] / (sums[13 + threadIdx.x] + 1e-5);
    __syncthreads();

    if (threadIdx.x == 0) {
        double accv = 0.0;
#pragma unroll
        for (int k = 0; k < 13; ++k) accv += ratios[k];
        const double bce = -sums[26] * inv_n * 0.6931471805599453; // log2 -> ln
        out[0] = (float)(bce + 1.0 - accv / 13.0);
    }
}

extern "C" void kernel_launch(void* const* d_in, const int* in_sizes, int n_in,
                              void* d_out, int out_size)
{
    const float* in = (const float*)d_in[0];
    const float* tg = (const float*)d_in[1];
    float* out = (float*)d_out;
    const int n = in_sizes[0];   // 18874368

    gc3d_main_kernel<<<NBLK, 128>>>(in, tg);
    gc3d_finalize_kernel<<<1, 864>>>(out, 1.0 / (double)n);
}